// round 10
// baseline (speedup 1.0000x reference)
#include <cuda_runtime.h>
#include <cuda_bf16.h>

// preds: [128, 4096, 50] float32 -> 26,214,400 elems (d_in[0])
// gt:    [128, 4096]     int32   ->    524,288 elems (d_in[1])
// out:   scalar float32
//
// loss = [ LN2*(sum_all log2(1+exp(p)) - sum_{unvoiced} log2(1+exp(p)))
//          - sum_{voiced} p.tgt ] / (50 * n_voiced)
//
// R6 two-phase structure (champion) + spill-proof phase-A diet:
//  - smem table t6[q][6]: tgt values on float2-aligned window [2c,2c+5],
//    c = max(q-2,0)>>1 (covers [q-2,q+2]; q<=24 so never crosses row end;
//    rows start at 200B -> 8B-aligned -> float2 legal for all rows)
//  - 3x LDG.64 + 6 FFMA per voiced row (was 5 scalar LDG + ~75 ALU recompute)
//  - unvoiced path NOT unrolled (R8's spill source removed)

#define NF4       6553600u
#define ROWS      524288u
#define NBINS     50

#define SP_BLOCKS  1184u         // 148 * 8, single wave
#define SP_THREADS 256u
#define NTHREADS   (SP_BLOCKS * SP_THREADS)   // 303104

__device__ float    g_part[SP_BLOCKS];
__device__ int      g_cntp[SP_BLOCKS];
__device__ unsigned g_done;              // ticket; reset by last block

__device__ __forceinline__ float gk(int i) {
    const float K0 = 2.6386456e-4f;
    const float K1 = 0.10645078f;
    const float K2 = 0.78657072f;
    return (i == 2) ? K2 : ((i == 1 || i == 3) ? K1 : K0);
}

__device__ __forceinline__ float sp2(float p) {   // log2(1 + exp(p))
    return __log2f(1.0f + __expf(p));
}

// prod *= (1 + exp(p))  ==  fma(prod, exp(p), prod)
__device__ __forceinline__ void pmul(float& pr, float p) {
    pr = fmaf(pr, __expf(p), pr);
}

__global__ __launch_bounds__(SP_THREADS, 8) void pitchloss_kernel(
    const float* __restrict__ preds, const int* __restrict__ gt,
    float* __restrict__ out)
{
    // ---- t6[q*6+j] = tgt at bin n = 2c+j (c = max(q-2,0)>>1), 1.2KB smem --
    __shared__ float t6[NBINS * 6];
    const int tid = threadIdx.x;
    if (tid < NBINS * 6) {
        int q = tid / 6, j = tid % 6;
        int c = (q >= 2) ? ((q - 2) >> 1) : 0;
        int n = 2 * c + j;
        float t = 0.0f;
        if (n < NBINS) {
            #pragma unroll
            for (int i = 0; i < 5; i++) {
                int m  = n + i - 2;
                int mm = (m < 0) ? -m : ((m > NBINS - 1) ? (2*(NBINS-1) - m) : m);
                if (mm == q) t += gk(i);
            }
        }
        t6[tid] = t;
    }
    __syncthreads();

    const unsigned gtid = blockIdx.x * SP_THREADS + tid;

    // ---------------- phase A: per-row work --------------------------------
    float dot = 0.0f, neg = 0.0f;
    int   cnt = 0;
    for (unsigned r = gtid; r < ROWS; r += NTHREADS) {
        int g = __ldg(gt + r);
        const float* row = preds + (size_t)r * NBINS;
        if (g != 100) {
            cnt++;
            int q = (g > 50) ? min((g - 50) / 6, NBINS - 1) : 0;
            int c = (q >= 2) ? ((q - 2) >> 1) : 0;
            const float2* w = reinterpret_cast<const float2*>(row) + c;
            float2 a = __ldg(w);
            float2 b = __ldg(w + 1);
            float2 d = __ldg(w + 2);
            int tb = q * 6;
            dot = fmaf(a.x, t6[tb + 0], dot);
            dot = fmaf(a.y, t6[tb + 1], dot);
            dot = fmaf(b.x, t6[tb + 2], dot);
            dot = fmaf(b.y, t6[tb + 3], dot);
            dot = fmaf(d.x, t6[tb + 4], dot);
            dot = fmaf(d.y, t6[tb + 5], dot);
        } else {
            // rare (~0.5%): keep live set tiny -- do NOT unroll
            #pragma unroll 1
            for (int n = 0; n < NBINS; n++)
                neg += sp2(__ldg(row + n));
        }
    }

    // ---------------- phase B: streaming softplus over ALL elements -------
    const float4* p4 = reinterpret_cast<const float4*>(preds);
    float acc = 0.0f;
    unsigned i = gtid;
    for (; i + 3u * NTHREADS < NF4; i += 4u * NTHREADS) {
        float4 a = p4[i];
        float4 b = p4[i +      NTHREADS];
        float4 c = p4[i + 2u * NTHREADS];
        float4 d = p4[i + 3u * NTHREADS];
        float pr1 = 1.0f + __expf(a.x);
        pmul(pr1, a.y); pmul(pr1, a.z); pmul(pr1, a.w);
        pmul(pr1, b.x); pmul(pr1, b.y); pmul(pr1, b.z); pmul(pr1, b.w);
        float pr2 = 1.0f + __expf(c.x);
        pmul(pr2, c.y); pmul(pr2, c.z); pmul(pr2, c.w);
        pmul(pr2, d.x); pmul(pr2, d.y); pmul(pr2, d.z); pmul(pr2, d.w);
        acc += __log2f(pr1) + __log2f(pr2);
    }
    for (; i < NF4; i += NTHREADS) {
        float4 a = p4[i];
        float pr = 1.0f + __expf(a.x);
        pmul(pr, a.y); pmul(pr, a.z); pmul(pr, a.w);
        acc += __log2f(pr);
    }

    // ---------------- block reduction -------------------------------------
    const float LN2 = 0.69314718055994530942f;
    float part = fmaf(LN2, acc - neg, -dot);

    __shared__ float sp[SP_THREADS];
    __shared__ int   sc[SP_THREADS];
    sp[tid] = part; sc[tid] = cnt;
    __syncthreads();
    #pragma unroll
    for (int o = SP_THREADS / 2; o > 0; o >>= 1) {
        if (tid < o) { sp[tid] += sp[tid + o]; sc[tid] += sc[tid + o]; }
        __syncthreads();
    }

    __shared__ bool s_last;
    if (tid == 0) {
        g_part[blockIdx.x] = sp[0];
        g_cntp[blockIdx.x] = sc[0];
        __threadfence();
        unsigned t = atomicAdd(&g_done, 1u);
        s_last = (t == SP_BLOCKS - 1);
    }
    __syncthreads();

    // ---------------- last block: deterministic ordered finalize ----------
    if (s_last) {
        float a = 0.0f; int c = 0;
        for (unsigned j = tid; j < SP_BLOCKS; j += SP_THREADS) {
            a += g_part[j]; c += g_cntp[j];
        }
        sp[tid] = a; sc[tid] = c;
        __syncthreads();
        #pragma unroll
        for (int o = SP_THREADS / 2; o > 0; o >>= 1) {
            if (tid < o) { sp[tid] += sp[tid + o]; sc[tid] += sc[tid + o]; }
            __syncthreads();
        }
        if (tid == 0) {
            out[0] = sp[0] / (50.0f * (float)sc[0]);
            g_done = 0;   // reset for next (graph-replayed) launch
        }
    }
}

extern "C" void kernel_launch(void* const* d_in, const int* in_sizes, int n_in,
                              void* d_out, int out_size)
{
    const float* preds = (const float*)d_in[0];
    const int*   gt    = (const int*)d_in[1];
    float* out = (float*)d_out;

    pitchloss_kernel<<<SP_BLOCKS, SP_THREADS>>>(preds, gt, out);
}